// round 13
// baseline (speedup 1.0000x reference)
#include <cuda_runtime.h>
#include <cuda_bf16.h>
#include <math.h>

// Problem constants (match reference)
#define NN 50000
#define EE 800000
#define ET (EE + NN)      // edges + self loops = 850000
#define DD 128            // gnn dim (all GEMM K = 128)
#define HH 256            // mlp hidden
#define CC 6              // labels
#define NB ((NN + 1023) / 1024)   // 49 scan blocks

// ---------------- scratch (device globals; no runtime allocation) -----------
__device__ float g_h0[(size_t)NN * DD];     // projected h (per layer)
__device__ float g_h1[(size_t)NN * DD];     // layer output / next input
__device__ float g_hid[(size_t)NN * HH];    // mlp hidden
__device__ float g_ssrc[NN];
__device__ float g_sdst[NN];
__device__ int   g_src[ET];
__device__ int   g_dst[ET];
__device__ int   g_srcs[ET];                // src sorted by dst segment
__device__ int   g_deg[NN];
__device__ int   g_offs[NN + 1];            // per-1024-block-local exclusive scan
__device__ int   g_fill[NN];
__device__ int   g_bsum[64];                // block offsets (exclusive)
__device__ int   g_is64;

// ---------------- merged dtype detection + counter init ---------------------
// int64 edge_index => every odd 32-bit word is 0 (values < 50000).
__global__ void detect_init_k(const unsigned int* __restrict__ w) {
    int i = blockIdx.x * blockDim.x + threadIdx.x;
    if (i < NN) { g_deg[i] = 0; g_fill[i] = 0; }
    if (blockIdx.x == 0) {
        __shared__ int any;
        if (threadIdx.x == 0) any = 0;
        __syncthreads();
        int t = 0;
        for (int j = threadIdx.x; j < 1024; j += blockDim.x)
            t |= (w[2 * j + 1] != 0u);
        if (t) any = 1;
        __syncthreads();
        if (threadIdx.x == 0) g_is64 = any ? 0 : 1;
    }
}

// Convert edge list (+ self loops), count in-degrees.
__global__ void build_k(const void* __restrict__ ei) {
    int i = blockIdx.x * blockDim.x + threadIdx.x;
    if (i >= ET) return;
    int s, d;
    if (i < EE) {
        if (g_is64) {
            const long long* p = (const long long*)ei;
            s = (int)p[i]; d = (int)p[EE + i];
        } else {
            const int* p = (const int*)ei;
            s = p[i]; d = p[EE + i];
        }
    } else {
        s = d = i - EE;   // self loop
    }
    g_src[i] = s; g_dst[i] = d;
    atomicAdd(&g_deg[d], 1);
}

// ---------------- 2-phase coalesced scan (R7-proven form) --------------------
__global__ void scan1_k() {
    __shared__ int wsum[32];
    int b = blockIdx.x, tid = threadIdx.x;
    int i = b * 1024 + tid;
    int v = (i < NN) ? g_deg[i] : 0;
    int lane = tid & 31, wid = tid >> 5;

    int inc = v;
#pragma unroll
    for (int o = 1; o < 32; o <<= 1) {
        int t = __shfl_up_sync(0xffffffffu, inc, o);
        if (lane >= o) inc += t;
    }
    if (lane == 31) wsum[wid] = inc;
    __syncthreads();
    if (wid == 0) {
        int w = wsum[lane];
#pragma unroll
        for (int o = 1; o < 32; o <<= 1) {
            int t = __shfl_up_sync(0xffffffffu, w, o);
            if (lane >= o) w += t;
        }
        wsum[lane] = w;
    }
    __syncthreads();
    int excl = inc - v + (wid ? wsum[wid - 1] : 0);
    if (i < NN) g_offs[i] = excl;            // block-local exclusive prefix
    if (tid == 1023) g_bsum[b] = excl + v;   // block total
}

__global__ void scan2_k() {
    int lane = threadIdx.x;       // 32 threads
    int v0 = (lane < NB) ? g_bsum[lane] : 0;
    int a = v0;
#pragma unroll
    for (int o = 1; o < 32; o <<= 1) {
        int t = __shfl_up_sync(0xffffffffu, a, o);
        if (lane >= o) a += t;
    }
    int tot32 = __shfl_sync(0xffffffffu, a, 31);
    int v1 = (lane + 32 < NB) ? g_bsum[lane + 32] : 0;
    int c = v1;
#pragma unroll
    for (int o = 1; o < 32; o <<= 1) {
        int t = __shfl_up_sync(0xffffffffu, c, o);
        if (lane >= o) c += t;
    }
    g_bsum[lane] = a - v0;                       // exclusive
    g_bsum[lane + 32] = (c - v1) + tot32;
}

__device__ __forceinline__ int seg_off(int i) {
    return (i == NN) ? ET : (g_offs[i] + g_bsum[i >> 10]);
}

// Bucket srcs by dst segment.
__global__ void scatter_k() {
    int i = blockIdx.x * blockDim.x + threadIdx.x;
    if (i >= ET) return;
    int d = g_dst[i];
    int pos = g_offs[d] + g_bsum[d >> 10] + atomicAdd(&g_fill[d], 1);
    g_srcs[pos] = g_src[i];
}

// ---------------- tf32x3 tensor-core GEMM + cp.async double buffering --------
// C[nrows, M] = A[nrows, 128] @ B[128, M] (+bias, relu). K fixed = 128.
// Block tile 128x128, 256 threads, 8 warps as 4(m) x 2(n); warp tile 32x64.
// 2-stage cp.async pipeline: chunk c+1 streams into smem while mma runs on c.

__device__ __forceinline__ unsigned f2tf(float x) {
    unsigned r;
    asm("cvt.rna.tf32.f32 %0, %1;" : "=r"(r) : "f"(x));
    return r;
}
__device__ __forceinline__ void split_tf(float x, unsigned& hi, unsigned& lo) {
    hi = f2tf(x);
    lo = f2tf(x - __uint_as_float(hi));
}
__device__ __forceinline__ void mma_tf32(float c[4],
    unsigned a0, unsigned a1, unsigned a2, unsigned a3,
    unsigned b0, unsigned b1)
{
    asm volatile(
        "mma.sync.aligned.m16n8k8.row.col.f32.tf32.tf32.f32 "
        "{%0,%1,%2,%3}, {%4,%5,%6,%7}, {%8,%9}, {%0,%1,%2,%3};"
        : "+f"(c[0]), "+f"(c[1]), "+f"(c[2]), "+f"(c[3])
        : "r"(a0), "r"(a1), "r"(a2), "r"(a3), "r"(b0), "r"(b1));
}
__device__ __forceinline__ void cpa16(void* smem_dst, const void* gsrc, int szbytes) {
    unsigned ds = (unsigned)__cvta_generic_to_shared(smem_dst);
    asm volatile("cp.async.cg.shared.global [%0], [%1], 16, %2;"
                 :: "r"(ds), "l"(gsrc), "r"(szbytes));
}

#define ASZ (128 * 36)   // floats per A stage (stride 36: conflict-free frags)
#define BSZ (32 * 136)   // floats per B stage (stride 136: conflict-free frags)
#define SGEMM_DYN ((2 * (ASZ + BSZ)) * (int)sizeof(float))   // 71680 B

__global__ __launch_bounds__(256) void sgemm_k(
    const float* __restrict__ A, const float* __restrict__ B,
    const float* __restrict__ bias, float* __restrict__ C,
    int nrows, int M, int doRelu,
    const float* __restrict__ asrc, const float* __restrict__ adst,
    float* __restrict__ ssrc_out, float* __restrict__ sdst_out)
{
    extern __shared__ float smem[];
    float* AsBase = smem;                 // 2 stages of [128][36]
    float* BsBase = smem + 2 * ASZ;       // 2 stages of [32][136]
    __shared__ float sdots[128][2];

    int tid  = threadIdx.x;
    int lane = tid & 31, w = tid >> 5;
    int g = lane >> 2, tg = lane & 3;
    int wm = w & 3, wn = w >> 2;          // warp grid 4(m) x 2(n)
    int m0 = wm * 32, n0 = wn * 64;
    int brow = blockIdx.x * 128;
    int bcol = blockIdx.y * 128;

    if (tid < 128) { sdots[tid][0] = 0.f; sdots[tid][1] = 0.f; }

    float Cacc[2][8][4];
#pragma unroll
    for (int ma = 0; ma < 2; ma++)
#pragma unroll
        for (int na = 0; na < 8; na++)
#pragma unroll
            for (int q = 0; q < 4; q++) Cacc[ma][na][q] = 0.f;

    // load mappings (per k-chunk of 32)
    int ar = tid >> 3;            // 0..31 A row group
    int ak = (tid & 7) * 4;       // 0..28
    int bk = tid >> 5;            // 0..7  B k group
    int bn = (tid & 31) * 4;      // 0..124

    // A row addresses (clamped; out-of-range rows copy 0 bytes => zero-fill)
    const float* Arow[4]; int Asz[4]; int Ar[4];
#pragma unroll
    for (int i = 0; i < 4; i++) {
        int r = ar + 32 * i;
        int grow = brow + r;
        Ar[i] = r;
        Asz[i] = (grow < nrows) ? 16 : 0;
        int cl = (grow < nrows) ? grow : (nrows - 1);
        Arow[i] = A + (size_t)cl * 128 + ak;
    }
    const float* Bp = B + (size_t)bk * M + bcol + bn;

    // ---- prologue: stage 0 <- chunk 0 ----
#pragma unroll
    for (int i = 0; i < 4; i++)
        cpa16(&AsBase[Ar[i] * 36 + ak], Arow[i], Asz[i]);
#pragma unroll
    for (int i = 0; i < 4; i++)
        cpa16(&BsBase[(bk + 8 * i) * 136 + bn], Bp + (size_t)(8 * i) * M, 16);
    asm volatile("cp.async.commit_group;");

    for (int c = 0; c < 4; c++) {
        int st = c & 1;
        if (c + 1 < 4) {
            int nst = (c + 1) & 1;
            int k0 = (c + 1) * 32;
#pragma unroll
            for (int i = 0; i < 4; i++)
                cpa16(&AsBase[nst * ASZ + Ar[i] * 36 + ak], Arow[i] + k0, Asz[i]);
#pragma unroll
            for (int i = 0; i < 4; i++)
                cpa16(&BsBase[nst * BSZ + (bk + 8 * i) * 136 + bn],
                      Bp + (size_t)(k0 + 8 * i) * M, 16);
            asm volatile("cp.async.commit_group;");
            asm volatile("cp.async.wait_group 1;");
        } else {
            asm volatile("cp.async.wait_group 0;");
        }
        __syncthreads();

        const float* As = AsBase + st * ASZ;
        const float* Bs = BsBase + st * BSZ;

#pragma unroll
        for (int ks = 0; ks < 4; ks++) {
            int kk = ks * 8;
            unsigned ahi[2][4], alo[2][4];
#pragma unroll
            for (int ma = 0; ma < 2; ma++) {
                int r0 = m0 + ma * 16 + g;
                split_tf(As[r0 * 36 + kk + tg],           ahi[ma][0], alo[ma][0]);
                split_tf(As[(r0 + 8) * 36 + kk + tg],     ahi[ma][1], alo[ma][1]);
                split_tf(As[r0 * 36 + kk + tg + 4],       ahi[ma][2], alo[ma][2]);
                split_tf(As[(r0 + 8) * 36 + kk + tg + 4], ahi[ma][3], alo[ma][3]);
            }
#pragma unroll
            for (int half = 0; half < 2; half++) {
                unsigned bhi[4][2], blo[4][2];
#pragma unroll
                for (int j = 0; j < 4; j++) {
                    int cn = n0 + (half * 4 + j) * 8 + g;
                    split_tf(Bs[(kk + tg) * 136 + cn],     bhi[j][0], blo[j][0]);
                    split_tf(Bs[(kk + tg + 4) * 136 + cn], bhi[j][1], blo[j][1]);
                }
#pragma unroll
                for (int ma = 0; ma < 2; ma++)
#pragma unroll
                    for (int j = 0; j < 4; j++) {
                        float* cc = Cacc[ma][half * 4 + j];
                        mma_tf32(cc, ahi[ma][0], ahi[ma][1], ahi[ma][2], ahi[ma][3],
                                     bhi[j][0], bhi[j][1]);
                        mma_tf32(cc, ahi[ma][0], ahi[ma][1], ahi[ma][2], ahi[ma][3],
                                     blo[j][0], blo[j][1]);
                        mma_tf32(cc, alo[ma][0], alo[ma][1], alo[ma][2], alo[ma][3],
                                     bhi[j][0], bhi[j][1]);
                    }
            }
        }
        __syncthreads();
    }

    // ---- fused attention dots (layer GEMMs only: M==128, bcol==0) ----
    if (asrc) {
#pragma unroll
        for (int ma = 0; ma < 2; ma++) {
            float ps0 = 0.f, pd0 = 0.f, ps1 = 0.f, pd1 = 0.f;
#pragma unroll
            for (int na = 0; na < 8; na++) {
                int cn = n0 + na * 8 + tg * 2;
                float a0v = asrc[cn], a1v = asrc[cn + 1];
                float d0v = adst[cn], d1v = adst[cn + 1];
                float* cc = Cacc[ma][na];
                ps0 += cc[0] * a0v + cc[1] * a1v;
                pd0 += cc[0] * d0v + cc[1] * d1v;
                ps1 += cc[2] * a0v + cc[3] * a1v;
                pd1 += cc[2] * d0v + cc[3] * d1v;
            }
#pragma unroll
            for (int o = 1; o < 4; o <<= 1) {
                ps0 += __shfl_xor_sync(0xffffffffu, ps0, o);
                pd0 += __shfl_xor_sync(0xffffffffu, pd0, o);
                ps1 += __shfl_xor_sync(0xffffffffu, ps1, o);
                pd1 += __shfl_xor_sync(0xffffffffu, pd1, o);
            }
            if (tg == 0) {
                int r0 = m0 + ma * 16 + g;
                atomicAdd(&sdots[r0][0], ps0);
                atomicAdd(&sdots[r0][1], pd0);
                atomicAdd(&sdots[r0 + 8][0], ps1);
                atomicAdd(&sdots[r0 + 8][1], pd1);
            }
        }
    }

    // ---- global stores ----
#pragma unroll
    for (int ma = 0; ma < 2; ma++) {
        int r0 = brow + m0 + ma * 16 + g;
#pragma unroll
        for (int na = 0; na < 8; na++) {
            int cn = bcol + n0 + na * 8 + tg * 2;
            float* cc = Cacc[ma][na];
            float v0 = cc[0], v1 = cc[1], v2 = cc[2], v3 = cc[3];
            if (bias) {
                float b0 = bias[cn], b1 = bias[cn + 1];
                v0 += b0; v1 += b1; v2 += b0; v3 += b1;
            }
            if (doRelu) {
                v0 = fmaxf(v0, 0.f); v1 = fmaxf(v1, 0.f);
                v2 = fmaxf(v2, 0.f); v3 = fmaxf(v3, 0.f);
            }
            if (r0 < nrows)     *(float2*)(C + (size_t)r0 * M + cn)       = make_float2(v0, v1);
            if (r0 + 8 < nrows) *(float2*)(C + (size_t)(r0 + 8) * M + cn) = make_float2(v2, v3);
        }
    }

    if (asrc) {
        __syncthreads();
        if (tid < 128) {
            int gr = brow + tid;
            if (gr < nrows) {
                ssrc_out[gr] = sdots[tid][0];
                sdst_out[gr] = sdots[tid][1];
            }
        }
    }
}

// ---------------- warp-per-dst-node segment softmax + weighted aggregate ----
// (R7-proven form)
__global__ void gat_agg_k(const float* __restrict__ h,
                          const float* __restrict__ bias,
                          float* __restrict__ out)
{
    int node = blockIdx.x * 8 + (threadIdx.x >> 5);
    int lane = threadIdx.x & 31;
    if (node >= NN) return;

    int beg = seg_off(node), end = seg_off(node + 1);
    float sd = g_sdst[node];

    // pass 1: online softmax (max + sum in one sweep)
    float mx = -3.4e38f, sum = 0.f;
    for (int e = beg + lane; e < end; e += 32) {
        float sc = g_ssrc[g_srcs[e]] + sd;
        sc = sc > 0.f ? sc : 0.2f * sc;
        float m2 = fmaxf(mx, sc);
        sum = sum * __expf(mx - m2) + __expf(sc - m2);
        mx = m2;
    }
    float wm = mx;
#pragma unroll
    for (int o = 16; o > 0; o >>= 1)
        wm = fmaxf(wm, __shfl_xor_sync(0xffffffffu, wm, o));
    sum *= __expf(mx - wm);
#pragma unroll
    for (int o = 16; o > 0; o >>= 1)
        sum += __shfl_xor_sync(0xffffffffu, sum, o);
    float inv = 1.f / sum;

    // pass 2: weighted row aggregation (full warp per edge, 4 floats/lane)
    float4 acc = make_float4(0.f, 0.f, 0.f, 0.f);
    for (int e = beg; e < end; e++) {
        int sv = g_srcs[e];
        float sc = g_ssrc[sv] + sd;            // broadcast L1 hit
        sc = sc > 0.f ? sc : 0.2f * sc;
        float w = __expf(sc - wm) * inv;
        float4 hv = *(const float4*)(h + (size_t)sv * DD + lane * 4);
        acc.x = fmaf(hv.x, w, acc.x);
        acc.y = fmaf(hv.y, w, acc.y);
        acc.z = fmaf(hv.z, w, acc.z);
        acc.w = fmaf(hv.w, w, acc.w);
    }

    float4 bv = *(const float4*)(bias + lane * 4);
    acc.x = fmaxf(acc.x + bv.x, 0.f);
    acc.y = fmaxf(acc.y + bv.y, 0.f);
    acc.z = fmaxf(acc.z + bv.z, 0.f);
    acc.w = fmaxf(acc.w + bv.w, 0.f);
    *(float4*)(out + (size_t)node * DD + lane * 4) = acc;
}

// ---------------- final tiny GEMM: out[N,6] = hid[N,256] @ Wm2 + bm2 --------
__global__ void mlp2_k(const float* __restrict__ hid,
                       const float* __restrict__ W,
                       const float* __restrict__ b,
                       float* __restrict__ out)
{
    int node = blockIdx.x * 8 + (threadIdx.x >> 5);
    int lane = threadIdx.x & 31;
    if (node >= NN) return;
    float acc[CC];
#pragma unroll
    for (int c = 0; c < CC; c++) acc[c] = 0.f;
#pragma unroll
    for (int i = 0; i < HH / 32; i++) {
        int k = lane + i * 32;
        float v = hid[(size_t)node * HH + k];
#pragma unroll
        for (int c = 0; c < CC; c++)
            acc[c] = fmaf(v, W[k * CC + c], acc[c]);
    }
#pragma unroll
    for (int c = 0; c < CC; c++) {
#pragma unroll
        for (int o = 16; o > 0; o >>= 1)
            acc[c] += __shfl_xor_sync(0xffffffffu, acc[c], o);
    }
    if (lane == 0) {
#pragma unroll
        for (int c = 0; c < CC; c++)
            out[(size_t)node * CC + c] = acc[c] + b[c];
    }
}

// ---------------- host launch ------------------------------------------------
static void* symaddr(const void* s) {
    void* p = nullptr;
    cudaGetSymbolAddress(&p, s);
    return p;
}

extern "C" void kernel_launch(void* const* d_in, const int* in_sizes, int n_in,
                              void* d_out, int out_size)
{
    const float* x   = (const float*)d_in[0];
    const void*  ei  = d_in[1];
    const float* W[3]  = { (const float*)d_in[2],  (const float*)d_in[6],  (const float*)d_in[10] };
    const float* b[3]  = { (const float*)d_in[3],  (const float*)d_in[7],  (const float*)d_in[11] };
    const float* as_[3]= { (const float*)d_in[4],  (const float*)d_in[8],  (const float*)d_in[12] };
    const float* ad_[3]= { (const float*)d_in[5],  (const float*)d_in[9],  (const float*)d_in[13] };
    const float* Wm1 = (const float*)d_in[14];
    const float* bm1 = (const float*)d_in[15];
    const float* Wm2 = (const float*)d_in[16];
    const float* bm2 = (const float*)d_in[17];
    float* out = (float*)d_out;

    float* h0  = (float*)symaddr(g_h0);
    float* h1  = (float*)symaddr(g_h1);
    float* hid = (float*)symaddr(g_hid);
    float* ssrc = (float*)symaddr(g_ssrc);
    float* sdst = (float*)symaddr(g_sdst);

    cudaFuncSetAttribute(sgemm_k, cudaFuncAttributeMaxDynamicSharedMemorySize,
                         SGEMM_DYN);

    // ---- graph preprocessing (R7-proven order: all preprocessing first) ----
    detect_init_k<<<(NN + 255) / 256, 256>>>((const unsigned int*)ei);
    build_k<<<(ET + 255) / 256, 256>>>(ei);
    scan1_k<<<NB, 1024>>>();
    scan2_k<<<1, 32>>>();
    scatter_k<<<(ET + 255) / 256, 256>>>();

    // ---- 3 GAT layers (attention dots fused into GEMM epilogue) ----
    const float* cur = x;
    for (int l = 0; l < 3; l++) {
        sgemm_k<<<dim3((NN + 127) / 128, 1), 256, SGEMM_DYN>>>(
            cur, W[l], nullptr, h0, NN, DD, 0,
            as_[l], ad_[l], ssrc, sdst);
        gat_agg_k<<<(NN + 7) / 8, 256>>>(h0, b[l], h1);
        cur = h1;
    }

    // ---- MLP head ----
    sgemm_k<<<dim3((NN + 127) / 128, 2), 256, SGEMM_DYN>>>(
        h1, Wm1, bm1, hid, NN, HH, 1,
        nullptr, nullptr, nullptr, nullptr);
    mlp2_k<<<(NN + 7) / 8, 256>>>(hid, Wm2, bm2, out);
}

// round 14
// speedup vs baseline: 1.1038x; 1.1038x over previous
#include <cuda_runtime.h>
#include <cuda_bf16.h>
#include <math.h>

// Problem constants (match reference)
#define NN 50000
#define EE 800000
#define ET (EE + NN)      // edges + self loops = 850000
#define DD 128            // gnn dim (all GEMM K = 128)
#define HH 256            // mlp hidden
#define CC 6              // labels
#define NB ((NN + 1023) / 1024)   // 49 scan blocks

// ---------------- scratch (device globals; no runtime allocation) -----------
__device__ float g_h0[(size_t)NN * DD];     // projected h (per layer)
__device__ float g_h1[(size_t)NN * DD];     // layer output / next input
__device__ float g_ssrc[NN];
__device__ float g_sdst[NN];
__device__ int   g_src[ET];
__device__ int   g_dst[ET];
__device__ int   g_srcs[ET];                // src sorted by dst segment
__device__ int   g_deg[NN];
__device__ int   g_offs[NN + 1];            // per-1024-block-local exclusive scan
__device__ int   g_fill[NN];
__device__ int   g_bsum[64];                // block offsets (exclusive)
__device__ int   g_is64;

// ---------------- merged dtype detection + counter init + out=bm2 -----------
// int64 edge_index => every odd 32-bit word is 0 (values < 50000).
__global__ void detect_init_k(const unsigned int* __restrict__ w,
                              const float* __restrict__ bm2,
                              float* __restrict__ out6) {
    int i = blockIdx.x * blockDim.x + threadIdx.x;
    if (i < NN) {
        g_deg[i] = 0; g_fill[i] = 0;
#pragma unroll
        for (int c = 0; c < CC; c++) out6[(size_t)i * CC + c] = bm2[c];
    }
    if (blockIdx.x == 0) {
        __shared__ int any;
        if (threadIdx.x == 0) any = 0;
        __syncthreads();
        int t = 0;
        for (int j = threadIdx.x; j < 1024; j += blockDim.x)
            t |= (w[2 * j + 1] != 0u);
        if (t) any = 1;
        __syncthreads();
        if (threadIdx.x == 0) g_is64 = any ? 0 : 1;
    }
}

// Convert edge list (+ self loops), count in-degrees.
__global__ void build_k(const void* __restrict__ ei) {
    int i = blockIdx.x * blockDim.x + threadIdx.x;
    if (i >= ET) return;
    int s, d;
    if (i < EE) {
        if (g_is64) {
            const long long* p = (const long long*)ei;
            s = (int)p[i]; d = (int)p[EE + i];
        } else {
            const int* p = (const int*)ei;
            s = p[i]; d = p[EE + i];
        }
    } else {
        s = d = i - EE;   // self loop
    }
    g_src[i] = s; g_dst[i] = d;
    atomicAdd(&g_deg[d], 1);
}

// ---------------- 2-phase coalesced scan (R7-proven form) --------------------
__global__ void scan1_k() {
    __shared__ int wsum[32];
    int b = blockIdx.x, tid = threadIdx.x;
    int i = b * 1024 + tid;
    int v = (i < NN) ? g_deg[i] : 0;
    int lane = tid & 31, wid = tid >> 5;

    int inc = v;
#pragma unroll
    for (int o = 1; o < 32; o <<= 1) {
        int t = __shfl_up_sync(0xffffffffu, inc, o);
        if (lane >= o) inc += t;
    }
    if (lane == 31) wsum[wid] = inc;
    __syncthreads();
    if (wid == 0) {
        int w = wsum[lane];
#pragma unroll
        for (int o = 1; o < 32; o <<= 1) {
            int t = __shfl_up_sync(0xffffffffu, w, o);
            if (lane >= o) w += t;
        }
        wsum[lane] = w;
    }
    __syncthreads();
    int excl = inc - v + (wid ? wsum[wid - 1] : 0);
    if (i < NN) g_offs[i] = excl;            // block-local exclusive prefix
    if (tid == 1023) g_bsum[b] = excl + v;   // block total
}

__global__ void scan2_k() {
    int lane = threadIdx.x;       // 32 threads
    int v0 = (lane < NB) ? g_bsum[lane] : 0;
    int a = v0;
#pragma unroll
    for (int o = 1; o < 32; o <<= 1) {
        int t = __shfl_up_sync(0xffffffffu, a, o);
        if (lane >= o) a += t;
    }
    int tot32 = __shfl_sync(0xffffffffu, a, 31);
    int v1 = (lane + 32 < NB) ? g_bsum[lane + 32] : 0;
    int c = v1;
#pragma unroll
    for (int o = 1; o < 32; o <<= 1) {
        int t = __shfl_up_sync(0xffffffffu, c, o);
        if (lane >= o) c += t;
    }
    g_bsum[lane] = a - v0;                       // exclusive
    g_bsum[lane + 32] = (c - v1) + tot32;
}

__device__ __forceinline__ int seg_off(int i) {
    return (i == NN) ? ET : (g_offs[i] + g_bsum[i >> 10]);
}

// Bucket srcs by dst segment.
__global__ void scatter_k() {
    int i = blockIdx.x * blockDim.x + threadIdx.x;
    if (i >= ET) return;
    int d = g_dst[i];
    int pos = g_offs[d] + g_bsum[d >> 10] + atomicAdd(&g_fill[d], 1);
    g_srcs[pos] = g_src[i];
}

// ---------------- tf32x3 tensor-core GEMM + cp.async double buffering --------
// C[nrows, M] = A[nrows, 128] @ B[128, M] (+bias, relu). K fixed = 128.
// Block tile 128x128, 256 threads, 8 warps as 4(m) x 2(n); warp tile 32x64.
// 2-stage cp.async pipeline: chunk c+1 streams into smem while mma runs on c.
// Modes:
//   asrc != null : layer GEMM; fuse ssrc/sdst attention dots, store C.
//   Wm2h != null : MLP head GEMM; do NOT store C; instead accumulate
//                  out6 += relu(C+bias) @ Wm2h via quad-reduce + atomicAdd.

__device__ __forceinline__ unsigned f2tf(float x) {
    unsigned r;
    asm("cvt.rna.tf32.f32 %0, %1;" : "=r"(r) : "f"(x));
    return r;
}
__device__ __forceinline__ void split_tf(float x, unsigned& hi, unsigned& lo) {
    hi = f2tf(x);
    lo = f2tf(x - __uint_as_float(hi));
}
__device__ __forceinline__ void mma_tf32(float c[4],
    unsigned a0, unsigned a1, unsigned a2, unsigned a3,
    unsigned b0, unsigned b1)
{
    asm volatile(
        "mma.sync.aligned.m16n8k8.row.col.f32.tf32.tf32.f32 "
        "{%0,%1,%2,%3}, {%4,%5,%6,%7}, {%8,%9}, {%0,%1,%2,%3};"
        : "+f"(c[0]), "+f"(c[1]), "+f"(c[2]), "+f"(c[3])
        : "r"(a0), "r"(a1), "r"(a2), "r"(a3), "r"(b0), "r"(b1));
}
__device__ __forceinline__ void cpa16(void* smem_dst, const void* gsrc, int szbytes) {
    unsigned ds = (unsigned)__cvta_generic_to_shared(smem_dst);
    asm volatile("cp.async.cg.shared.global [%0], [%1], 16, %2;"
                 :: "r"(ds), "l"(gsrc), "r"(szbytes));
}

#define ASZ (128 * 36)   // floats per A stage (stride 36: conflict-free frags)
#define BSZ (32 * 136)   // floats per B stage (stride 136: conflict-free frags)
#define SGEMM_DYN ((2 * (ASZ + BSZ)) * (int)sizeof(float))   // 71680 B

__global__ __launch_bounds__(256) void sgemm_k(
    const float* __restrict__ A, const float* __restrict__ B,
    const float* __restrict__ bias, float* __restrict__ C,
    int nrows, int M, int doRelu,
    const float* __restrict__ asrc, const float* __restrict__ adst,
    float* __restrict__ ssrc_out, float* __restrict__ sdst_out,
    const float* __restrict__ Wm2h, float* __restrict__ out6)
{
    extern __shared__ float smem[];
    float* AsBase = smem;                 // 2 stages of [128][36]
    float* BsBase = smem + 2 * ASZ;       // 2 stages of [32][136]
    __shared__ float sdots[128][2];

    int tid  = threadIdx.x;
    int lane = tid & 31, w = tid >> 5;
    int g = lane >> 2, tg = lane & 3;
    int wm = w & 3, wn = w >> 2;          // warp grid 4(m) x 2(n)
    int m0 = wm * 32, n0 = wn * 64;
    int brow = blockIdx.x * 128;
    int bcol = blockIdx.y * 128;

    if (tid < 128) { sdots[tid][0] = 0.f; sdots[tid][1] = 0.f; }

    float Cacc[2][8][4];
#pragma unroll
    for (int ma = 0; ma < 2; ma++)
#pragma unroll
        for (int na = 0; na < 8; na++)
#pragma unroll
            for (int q = 0; q < 4; q++) Cacc[ma][na][q] = 0.f;

    // load mappings (per k-chunk of 32)
    int ar = tid >> 3;            // 0..31 A row group
    int ak = (tid & 7) * 4;       // 0..28
    int bk = tid >> 5;            // 0..7  B k group
    int bn = (tid & 31) * 4;      // 0..124

    // A row addresses (clamped; out-of-range rows copy 0 bytes => zero-fill)
    const float* Arow[4]; int Asz[4]; int Ar[4];
#pragma unroll
    for (int i = 0; i < 4; i++) {
        int r = ar + 32 * i;
        int grow = brow + r;
        Ar[i] = r;
        Asz[i] = (grow < nrows) ? 16 : 0;
        int cl = (grow < nrows) ? grow : (nrows - 1);
        Arow[i] = A + (size_t)cl * 128 + ak;
    }
    const float* Bp = B + (size_t)bk * M + bcol + bn;

    // ---- prologue: stage 0 <- chunk 0 ----
#pragma unroll
    for (int i = 0; i < 4; i++)
        cpa16(&AsBase[Ar[i] * 36 + ak], Arow[i], Asz[i]);
#pragma unroll
    for (int i = 0; i < 4; i++)
        cpa16(&BsBase[(bk + 8 * i) * 136 + bn], Bp + (size_t)(8 * i) * M, 16);
    asm volatile("cp.async.commit_group;");

    for (int c = 0; c < 4; c++) {
        int st = c & 1;
        if (c + 1 < 4) {
            int nst = (c + 1) & 1;
            int k0 = (c + 1) * 32;
#pragma unroll
            for (int i = 0; i < 4; i++)
                cpa16(&AsBase[nst * ASZ + Ar[i] * 36 + ak], Arow[i] + k0, Asz[i]);
#pragma unroll
            for (int i = 0; i < 4; i++)
                cpa16(&BsBase[nst * BSZ + (bk + 8 * i) * 136 + bn],
                      Bp + (size_t)(k0 + 8 * i) * M, 16);
            asm volatile("cp.async.commit_group;");
            asm volatile("cp.async.wait_group 1;");
        } else {
            asm volatile("cp.async.wait_group 0;");
        }
        __syncthreads();

        const float* As = AsBase + st * ASZ;
        const float* Bs = BsBase + st * BSZ;

#pragma unroll
        for (int ks = 0; ks < 4; ks++) {
            int kk = ks * 8;
            unsigned ahi[2][4], alo[2][4];
#pragma unroll
            for (int ma = 0; ma < 2; ma++) {
                int r0 = m0 + ma * 16 + g;
                split_tf(As[r0 * 36 + kk + tg],           ahi[ma][0], alo[ma][0]);
                split_tf(As[(r0 + 8) * 36 + kk + tg],     ahi[ma][1], alo[ma][1]);
                split_tf(As[r0 * 36 + kk + tg + 4],       ahi[ma][2], alo[ma][2]);
                split_tf(As[(r0 + 8) * 36 + kk + tg + 4], ahi[ma][3], alo[ma][3]);
            }
#pragma unroll
            for (int half = 0; half < 2; half++) {
                unsigned bhi[4][2], blo[4][2];
#pragma unroll
                for (int j = 0; j < 4; j++) {
                    int cn = n0 + (half * 4 + j) * 8 + g;
                    split_tf(Bs[(kk + tg) * 136 + cn],     bhi[j][0], blo[j][0]);
                    split_tf(Bs[(kk + tg + 4) * 136 + cn], bhi[j][1], blo[j][1]);
                }
#pragma unroll
                for (int ma = 0; ma < 2; ma++)
#pragma unroll
                    for (int j = 0; j < 4; j++) {
                        float* cc = Cacc[ma][half * 4 + j];
                        mma_tf32(cc, ahi[ma][0], ahi[ma][1], ahi[ma][2], ahi[ma][3],
                                     bhi[j][0], bhi[j][1]);
                        mma_tf32(cc, ahi[ma][0], ahi[ma][1], ahi[ma][2], ahi[ma][3],
                                     blo[j][0], blo[j][1]);
                        mma_tf32(cc, alo[ma][0], alo[ma][1], alo[ma][2], alo[ma][3],
                                     bhi[j][0], bhi[j][1]);
                    }
            }
        }
        __syncthreads();
    }

    // ---- fused attention dots (layer GEMMs only: M==128, bcol==0) ----
    if (asrc) {
#pragma unroll
        for (int ma = 0; ma < 2; ma++) {
            float ps0 = 0.f, pd0 = 0.f, ps1 = 0.f, pd1 = 0.f;
#pragma unroll
            for (int na = 0; na < 8; na++) {
                int cn = n0 + na * 8 + tg * 2;
                float a0v = asrc[cn], a1v = asrc[cn + 1];
                float d0v = adst[cn], d1v = adst[cn + 1];
                float* cc = Cacc[ma][na];
                ps0 += cc[0] * a0v + cc[1] * a1v;
                pd0 += cc[0] * d0v + cc[1] * d1v;
                ps1 += cc[2] * a0v + cc[3] * a1v;
                pd1 += cc[2] * d0v + cc[3] * d1v;
            }
#pragma unroll
            for (int o = 1; o < 4; o <<= 1) {
                ps0 += __shfl_xor_sync(0xffffffffu, ps0, o);
                pd0 += __shfl_xor_sync(0xffffffffu, pd0, o);
                ps1 += __shfl_xor_sync(0xffffffffu, ps1, o);
                pd1 += __shfl_xor_sync(0xffffffffu, pd1, o);
            }
            if (tg == 0) {
                int r0 = m0 + ma * 16 + g;
                atomicAdd(&sdots[r0][0], ps0);
                atomicAdd(&sdots[r0][1], pd0);
                atomicAdd(&sdots[r0 + 8][0], ps1);
                atomicAdd(&sdots[r0 + 8][1], pd1);
            }
        }
    }

    if (Wm2h) {
        // ---- fused MLP head: out6 += relu(Cacc + bias) @ Wm2h ----
        // No C store at all (hid never materialized).
#pragma unroll
        for (int ma = 0; ma < 2; ma++) {
            float pa[CC], pb[CC];
#pragma unroll
            for (int cix = 0; cix < CC; cix++) { pa[cix] = 0.f; pb[cix] = 0.f; }
#pragma unroll
            for (int na = 0; na < 8; na++) {
                int cn = bcol + n0 + na * 8 + tg * 2;
                float b0 = bias[cn], b1 = bias[cn + 1];
                float* cc = Cacc[ma][na];
                float v0 = fmaxf(cc[0] + b0, 0.f);
                float v1 = fmaxf(cc[1] + b1, 0.f);
                float v2 = fmaxf(cc[2] + b0, 0.f);
                float v3 = fmaxf(cc[3] + b1, 0.f);
                const float* w0 = Wm2h + (size_t)cn * CC;
                const float* w1 = w0 + CC;
#pragma unroll
                for (int cix = 0; cix < CC; cix++) {
                    pa[cix] = fmaf(v0, w0[cix], fmaf(v1, w1[cix], pa[cix]));
                    pb[cix] = fmaf(v2, w0[cix], fmaf(v3, w1[cix], pb[cix]));
                }
            }
            // reduce across the 4 tg lanes holding this row's columns
#pragma unroll
            for (int o = 1; o < 4; o <<= 1) {
#pragma unroll
                for (int cix = 0; cix < CC; cix++) {
                    pa[cix] += __shfl_xor_sync(0xffffffffu, pa[cix], o);
                    pb[cix] += __shfl_xor_sync(0xffffffffu, pb[cix], o);
                }
            }
            if (tg == 0) {
                int r0 = brow + m0 + ma * 16 + g;
                if (r0 < nrows) {
#pragma unroll
                    for (int cix = 0; cix < CC; cix++)
                        atomicAdd(out6 + (size_t)r0 * CC + cix, pa[cix]);
                }
                if (r0 + 8 < nrows) {
#pragma unroll
                    for (int cix = 0; cix < CC; cix++)
                        atomicAdd(out6 + (size_t)(r0 + 8) * CC + cix, pb[cix]);
                }
            }
        }
    } else {
        // ---- global stores ----
#pragma unroll
        for (int ma = 0; ma < 2; ma++) {
            int r0 = brow + m0 + ma * 16 + g;
#pragma unroll
            for (int na = 0; na < 8; na++) {
                int cn = bcol + n0 + na * 8 + tg * 2;
                float* cc = Cacc[ma][na];
                float v0 = cc[0], v1 = cc[1], v2 = cc[2], v3 = cc[3];
                if (bias) {
                    float b0 = bias[cn], b1 = bias[cn + 1];
                    v0 += b0; v1 += b1; v2 += b0; v3 += b1;
                }
                if (doRelu) {
                    v0 = fmaxf(v0, 0.f); v1 = fmaxf(v1, 0.f);
                    v2 = fmaxf(v2, 0.f); v3 = fmaxf(v3, 0.f);
                }
                if (r0 < nrows)     *(float2*)(C + (size_t)r0 * M + cn)       = make_float2(v0, v1);
                if (r0 + 8 < nrows) *(float2*)(C + (size_t)(r0 + 8) * M + cn) = make_float2(v2, v3);
            }
        }
    }

    if (asrc) {
        __syncthreads();
        if (tid < 128) {
            int gr = brow + tid;
            if (gr < nrows) {
                ssrc_out[gr] = sdots[tid][0];
                sdst_out[gr] = sdots[tid][1];
            }
        }
    }
}

// ---------------- warp-per-dst-node segment softmax + weighted aggregate ----
// (R7-proven form)
__global__ void gat_agg_k(const float* __restrict__ h,
                          const float* __restrict__ bias,
                          float* __restrict__ out)
{
    int node = blockIdx.x * 8 + (threadIdx.x >> 5);
    int lane = threadIdx.x & 31;
    if (node >= NN) return;

    int beg = seg_off(node), end = seg_off(node + 1);
    float sd = g_sdst[node];

    // pass 1: online softmax (max + sum in one sweep)
    float mx = -3.4e38f, sum = 0.f;
    for (int e = beg + lane; e < end; e += 32) {
        float sc = g_ssrc[g_srcs[e]] + sd;
        sc = sc > 0.f ? sc : 0.2f * sc;
        float m2 = fmaxf(mx, sc);
        sum = sum * __expf(mx - m2) + __expf(sc - m2);
        mx = m2;
    }
    float wm = mx;
#pragma unroll
    for (int o = 16; o > 0; o >>= 1)
        wm = fmaxf(wm, __shfl_xor_sync(0xffffffffu, wm, o));
    sum *= __expf(mx - wm);
#pragma unroll
    for (int o = 16; o > 0; o >>= 1)
        sum += __shfl_xor_sync(0xffffffffu, sum, o);
    float inv = 1.f / sum;

    // pass 2: weighted row aggregation (full warp per edge, 4 floats/lane)
    float4 acc = make_float4(0.f, 0.f, 0.f, 0.f);
    for (int e = beg; e < end; e++) {
        int sv = g_srcs[e];
        float sc = g_ssrc[sv] + sd;            // broadcast L1 hit
        sc = sc > 0.f ? sc : 0.2f * sc;
        float w = __expf(sc - wm) * inv;
        float4 hv = *(const float4*)(h + (size_t)sv * DD + lane * 4);
        acc.x = fmaf(hv.x, w, acc.x);
        acc.y = fmaf(hv.y, w, acc.y);
        acc.z = fmaf(hv.z, w, acc.z);
        acc.w = fmaf(hv.w, w, acc.w);
    }

    float4 bv = *(const float4*)(bias + lane * 4);
    acc.x = fmaxf(acc.x + bv.x, 0.f);
    acc.y = fmaxf(acc.y + bv.y, 0.f);
    acc.z = fmaxf(acc.z + bv.z, 0.f);
    acc.w = fmaxf(acc.w + bv.w, 0.f);
    *(float4*)(out + (size_t)node * DD + lane * 4) = acc;
}

// ---------------- host launch ------------------------------------------------
static void* symaddr(const void* s) {
    void* p = nullptr;
    cudaGetSymbolAddress(&p, s);
    return p;
}

extern "C" void kernel_launch(void* const* d_in, const int* in_sizes, int n_in,
                              void* d_out, int out_size)
{
    const float* x   = (const float*)d_in[0];
    const void*  ei  = d_in[1];
    const float* W[3]  = { (const float*)d_in[2],  (const float*)d_in[6],  (const float*)d_in[10] };
    const float* b[3]  = { (const float*)d_in[3],  (const float*)d_in[7],  (const float*)d_in[11] };
    const float* as_[3]= { (const float*)d_in[4],  (const float*)d_in[8],  (const float*)d_in[12] };
    const float* ad_[3]= { (const float*)d_in[5],  (const float*)d_in[9],  (const float*)d_in[13] };
    const float* Wm1 = (const float*)d_in[14];
    const float* bm1 = (const float*)d_in[15];
    const float* Wm2 = (const float*)d_in[16];
    const float* bm2 = (const float*)d_in[17];
    float* out = (float*)d_out;

    float* h0  = (float*)symaddr(g_h0);
    float* h1  = (float*)symaddr(g_h1);
    float* ssrc = (float*)symaddr(g_ssrc);
    float* sdst = (float*)symaddr(g_sdst);

    cudaFuncSetAttribute(sgemm_k, cudaFuncAttributeMaxDynamicSharedMemorySize,
                         SGEMM_DYN);

    // ---- graph preprocessing (also pre-seeds out with bm2 for fused head) ----
    detect_init_k<<<(NN + 255) / 256, 256>>>((const unsigned int*)ei, bm2, out);
    build_k<<<(ET + 255) / 256, 256>>>(ei);
    scan1_k<<<NB, 1024>>>();
    scan2_k<<<1, 32>>>();
    scatter_k<<<(ET + 255) / 256, 256>>>();

    // ---- 3 GAT layers (attention dots fused into GEMM epilogue) ----
    const float* cur = x;
    for (int l = 0; l < 3; l++) {
        sgemm_k<<<dim3((NN + 127) / 128, 1), 256, SGEMM_DYN>>>(
            cur, W[l], nullptr, h0, NN, DD, 0,
            as_[l], ad_[l], ssrc, sdst, nullptr, nullptr);
        gat_agg_k<<<(NN + 7) / 8, 256>>>(h0, b[l], h1);
        cur = h1;
    }

    // ---- MLP head fully fused into one GEMM (hid never materialized) ----
    sgemm_k<<<dim3((NN + 127) / 128, 2), 256, SGEMM_DYN>>>(
        h1, Wm1, bm1, h0 /*unused*/, NN, HH, 1,
        nullptr, nullptr, nullptr, nullptr, Wm2, out);
}